// round 2
// baseline (speedup 1.0000x reference)
#include <cuda_runtime.h>
#include <math.h>

#define B_   4
#define S_   2048
#define EMB_ 1024
#define H_   16
#define HD_  64
#define M_   (B_ * S_)   // 8192

typedef unsigned long long ull;
struct __align__(16) u64x2 { ull x, y; };

// ---- packed fp32x2 helpers -------------------------------------------------
__device__ __forceinline__ ull pack2(float lo, float hi) {
    ull r; asm("mov.b64 %0, {%1, %2};" : "=l"(r) : "f"(lo), "f"(hi)); return r;
}
__device__ __forceinline__ ull bcast2(float v) {
    ull r; asm("mov.b64 %0, {%1, %1};" : "=l"(r) : "f"(v)); return r;
}
__device__ __forceinline__ ull fma2(ull a, ull b, ull c) {
    ull d; asm("fma.rn.f32x2 %0, %1, %2, %3;" : "=l"(d) : "l"(a), "l"(b), "l"(c)); return d;
}
__device__ __forceinline__ ull mul2(ull a, ull b) {
    ull d; asm("mul.rn.f32x2 %0, %1, %2;" : "=l"(d) : "l"(a), "l"(b)); return d;
}
__device__ __forceinline__ float2 unpack2(ull v) {
    float2 f; asm("mov.b64 {%0, %1}, %2;" : "=f"(f.x), "=f"(f.y) : "l"(v)); return f;
}

// ---------------- scratch (device globals; no allocation allowed) ----------
__device__ float g_q[(size_t)B_ * H_ * S_ * HD_];
__device__ float g_k[(size_t)B_ * H_ * S_ * HD_];
__device__ float g_v[(size_t)B_ * H_ * S_ * HD_];
__device__ float g_attn[(size_t)M_ * EMB_];

// ---------------- GEMM: Y = A @ W^T  (A:[M,K] row-major, W:[N,K] row-major) -
constexpr int BM = 128, BN = 128, BK = 8;

__device__ __forceinline__ void gemm_core(const float* __restrict__ A,
                                          const float* __restrict__ W,
                                          ull acc2[8][4],
                                          int row0, int col0, int Kdim)
{
    __shared__ float As[BK][BM + 4];
    __shared__ float Bs[BK][BN + 4];

    const int t  = threadIdx.x;
    const int lr = t >> 1;            // 0..127 (tile row for loads)
    const int lc = (t & 1) * 4;       // 0 or 4 (k-offset for loads)
    const int ty = t >> 4;            // 0..15
    const int tx = t & 15;            // 0..15

    const float* aptr = A + (size_t)(row0 + lr) * Kdim + lc;
    const float* wptr = W + (size_t)(col0 + lr) * Kdim + lc;

    for (int kb = 0; kb < Kdim; kb += BK) {
        float4 av = *(const float4*)(aptr + kb);
        float4 wv = *(const float4*)(wptr + kb);
        As[lc + 0][lr] = av.x; As[lc + 1][lr] = av.y;
        As[lc + 2][lr] = av.z; As[lc + 3][lr] = av.w;
        Bs[lc + 0][lr] = wv.x; Bs[lc + 1][lr] = wv.y;
        Bs[lc + 2][lr] = wv.z; Bs[lc + 3][lr] = wv.w;
        __syncthreads();

        #pragma unroll
        for (int k = 0; k < BK; ++k) {
            float a[8];
            *(float4*)(a)     = *(const float4*)&As[k][ty * 8];
            *(float4*)(a + 4) = *(const float4*)&As[k][ty * 8 + 4];
            u64x2 b01 = *(const u64x2*)&Bs[k][tx * 8];
            u64x2 b23 = *(const u64x2*)&Bs[k][tx * 8 + 4];
            #pragma unroll
            for (int i = 0; i < 8; ++i) {
                ull ai = bcast2(a[i]);
                acc2[i][0] = fma2(ai, b01.x, acc2[i][0]);
                acc2[i][1] = fma2(ai, b01.y, acc2[i][1]);
                acc2[i][2] = fma2(ai, b23.x, acc2[i][2]);
                acc2[i][3] = fma2(ai, b23.y, acc2[i][3]);
            }
        }
        __syncthreads();
    }
}

// QKV projection: blockIdx.z selects {Q,K,V}; epilogue scatters to [B,H,S,hd]
__global__ __launch_bounds__(256) void qkv_kernel(
    const float* __restrict__ x,
    const float* __restrict__ Wq, const float* __restrict__ bq,
    const float* __restrict__ Wk, const float* __restrict__ bk,
    const float* __restrict__ Wv, const float* __restrict__ bv)
{
    const float* W;  const float* bias;  float* out;
    if (blockIdx.z == 0)      { W = Wq; bias = bq; out = g_q; }
    else if (blockIdx.z == 1) { W = Wk; bias = bk; out = g_k; }
    else                      { W = Wv; bias = bv; out = g_v; }

    const int row0 = blockIdx.y * BM;
    const int col0 = blockIdx.x * BN;

    ull acc2[8][4] = {};
    gemm_core(x, W, acc2, row0, col0, EMB_);

    const int ty = threadIdx.x >> 4, tx = threadIdx.x & 15;
    #pragma unroll
    for (int i = 0; i < 8; ++i) {
        int m  = row0 + ty * 8 + i;
        int bb = m / S_;
        int s  = m % S_;
        float a8[8];
        #pragma unroll
        for (int jp = 0; jp < 4; ++jp) {
            float2 f = unpack2(acc2[i][jp]);
            a8[jp * 2] = f.x; a8[jp * 2 + 1] = f.y;
        }
        #pragma unroll
        for (int j0 = 0; j0 < 8; j0 += 4) {
            int n = col0 + tx * 8 + j0;
            int h = n >> 6, d = n & 63;
            float4 v;
            v.x = a8[j0 + 0] + bias[n + 0];
            v.y = a8[j0 + 1] + bias[n + 1];
            v.z = a8[j0 + 2] + bias[n + 2];
            v.w = a8[j0 + 3] + bias[n + 3];
            *(float4*)&out[(((size_t)bb * H_ + h) * S_ + s) * HD_ + d] = v;
        }
    }
}

// Output projection: d_out = g_attn @ Wo^T + bo
__global__ __launch_bounds__(256) void oproj_kernel(
    const float* __restrict__ Wo, const float* __restrict__ bo,
    float* __restrict__ out)
{
    const int row0 = blockIdx.y * BM;
    const int col0 = blockIdx.x * BN;

    ull acc2[8][4] = {};
    gemm_core(g_attn, Wo, acc2, row0, col0, EMB_);

    const int ty = threadIdx.x >> 4, tx = threadIdx.x & 15;
    #pragma unroll
    for (int i = 0; i < 8; ++i) {
        int m = row0 + ty * 8 + i;
        float a8[8];
        #pragma unroll
        for (int jp = 0; jp < 4; ++jp) {
            float2 f = unpack2(acc2[i][jp]);
            a8[jp * 2] = f.x; a8[jp * 2 + 1] = f.y;
        }
        #pragma unroll
        for (int j0 = 0; j0 < 8; j0 += 4) {
            int n = col0 + tx * 8 + j0;
            float4 v;
            v.x = a8[j0 + 0] + bo[n + 0];
            v.y = a8[j0 + 1] + bo[n + 1];
            v.z = a8[j0 + 2] + bo[n + 2];
            v.w = a8[j0 + 3] + bo[n + 3];
            *(float4*)&out[(size_t)m * EMB_ + n] = v;
        }
    }
}

// ---------------- causal flash attention (fp32x2, online softmax) ----------
constexpr int AT   = 64;    // q/k tile
constexpr int APAD = 68;    // padded row stride (floats)
constexpr int ATTN_SMEM = 4 * AT * APAD * (int)sizeof(float);  // 69632 B

__global__ __launch_bounds__(256) void attn_kernel()
{
    extern __shared__ float sm[];
    float (*Qs)[APAD] = (float(*)[APAD])(sm);
    float (*Kt)[APAD] = (float(*)[APAD])(sm + 1 * AT * APAD);  // transposed: Kt[d][k]
    float (*Vs)[APAD] = (float(*)[APAD])(sm + 2 * AT * APAD);
    float (*Ps)[APAD] = (float(*)[APAD])(sm + 3 * AT * APAD);

    const int qt = blockIdx.x;          // q tile index (0..31)
    const int bh = blockIdx.y;          // b*H + h     (0..63)
    const float* Qg = g_q + (size_t)bh * S_ * HD_;
    const float* Kg = g_k + (size_t)bh * S_ * HD_;
    const float* Vg = g_v + (size_t)bh * S_ * HD_;

    const int t  = threadIdx.x;
    const int tx = t & 15;              // col group (k cols / head dims)
    const int ty = t >> 4;              // row group (q rows)

    // Load Q tile once (64x64 floats)
    #pragma unroll
    for (int r = 0; r < 4; ++r) {
        int id  = t + r * 256;
        int row = id >> 4;
        int c4  = (id & 15) * 4;
        *(float4*)&Qs[row][c4] =
            *(const float4*)&Qg[(size_t)(qt * AT + row) * HD_ + c4];
    }

    float m[4], l[4];
    ull acc2[4][2];
    #pragma unroll
    for (int i = 0; i < 4; ++i) {
        m[i] = -1e30f; l[i] = 0.0f;
        acc2[i][0] = 0ull; acc2[i][1] = 0ull;
    }
    const float scale = 0.125f;  // 1/sqrt(64)

    for (int kt = 0; kt <= qt; ++kt) {
        __syncthreads();  // previous PV reads (and Q load on iter 0) done

        // Load K tile transposed + V tile
        #pragma unroll
        for (int r = 0; r < 4; ++r) {
            int id  = t + r * 256;
            int row = id >> 4;
            int c4  = (id & 15) * 4;
            float4 kv = *(const float4*)&Kg[(size_t)(kt * AT + row) * HD_ + c4];
            Kt[c4 + 0][row] = kv.x; Kt[c4 + 1][row] = kv.y;
            Kt[c4 + 2][row] = kv.z; Kt[c4 + 3][row] = kv.w;
            *(float4*)&Vs[row][c4] =
                *(const float4*)&Vg[(size_t)(kt * AT + row) * HD_ + c4];
        }
        __syncthreads();

        // S = (Q K^T) * scale   (packed f32x2 along the 4 k-columns)
        ull s2[4][2] = {};
        #pragma unroll
        for (int d4 = 0; d4 < 16; ++d4) {
            float4 q4[4];
            #pragma unroll
            for (int i = 0; i < 4; ++i)
                q4[i] = *(const float4*)&Qs[ty * 4 + i][d4 * 4];
            #pragma unroll
            for (int dd = 0; dd < 4; ++dd) {
                u64x2 k2 = *(const u64x2*)&Kt[d4 * 4 + dd][tx * 4];
                #pragma unroll
                for (int i = 0; i < 4; ++i) {
                    ull qv = bcast2(((const float*)&q4[i])[dd]);
                    s2[i][0] = fma2(qv, k2.x, s2[i][0]);
                    s2[i][1] = fma2(qv, k2.y, s2[i][1]);
                }
            }
        }

        // unpack, scale, causal mask
        float s[4][4];
        const bool diag = (kt == qt);
        #pragma unroll
        for (int i = 0; i < 4; ++i) {
            int li = ty * 4 + i;  // local q row
            float2 f0 = unpack2(s2[i][0]);
            float2 f1 = unpack2(s2[i][1]);
            s[i][0] = f0.x * scale; s[i][1] = f0.y * scale;
            s[i][2] = f1.x * scale; s[i][3] = f1.y * scale;
            if (diag) {
                #pragma unroll
                for (int j = 0; j < 4; ++j)
                    if ((tx * 4 + j) > li) s[i][j] = -1e30f;
            }
        }

        // Online softmax (row groups = 16-lane half-warps: shfl_xor 8..1)
        #pragma unroll
        for (int i = 0; i < 4; ++i) {
            float mx = fmaxf(fmaxf(s[i][0], s[i][1]), fmaxf(s[i][2], s[i][3]));
            #pragma unroll
            for (int o = 8; o >= 1; o >>= 1)
                mx = fmaxf(mx, __shfl_xor_sync(0xffffffffu, mx, o));
            float newm = fmaxf(m[i], mx);
            float f    = __expf(m[i] - newm);
            float psum = 0.0f;
            #pragma unroll
            for (int j = 0; j < 4; ++j) {
                float p = __expf(s[i][j] - newm);
                s[i][j] = p;
                psum += p;
            }
            #pragma unroll
            for (int o = 8; o >= 1; o >>= 1)
                psum += __shfl_xor_sync(0xffffffffu, psum, o);
            l[i] = l[i] * f + psum;
            m[i] = newm;
            ull fp = bcast2(f);
            acc2[i][0] = mul2(acc2[i][0], fp);
            acc2[i][1] = mul2(acc2[i][1], fp);
            *(float4*)&Ps[ty * 4 + i][tx * 4] = *(float4*)&s[i][0];
        }
        __syncthreads();

        // O += P @ V   (packed along the 4 head-dim columns)
        #pragma unroll
        for (int k4 = 0; k4 < 16; ++k4) {
            float4 p4[4];
            #pragma unroll
            for (int i = 0; i < 4; ++i)
                p4[i] = *(const float4*)&Ps[ty * 4 + i][k4 * 4];
            #pragma unroll
            for (int kk = 0; kk < 4; ++kk) {
                u64x2 v2 = *(const u64x2*)&Vs[k4 * 4 + kk][tx * 4];
                #pragma unroll
                for (int i = 0; i < 4; ++i) {
                    ull pv = bcast2(((const float*)&p4[i])[kk]);
                    acc2[i][0] = fma2(pv, v2.x, acc2[i][0]);
                    acc2[i][1] = fma2(pv, v2.y, acc2[i][1]);
                }
            }
        }
    }

    // Epilogue: normalize, scatter to [B, S, EMB] for the output projection
    const int b = bh / H_, h = bh % H_;
    #pragma unroll
    for (int i = 0; i < 4; ++i) {
        float inv = 1.0f / l[i];
        int srow  = qt * AT + ty * 4 + i;
        float2 f0 = unpack2(acc2[i][0]);
        float2 f1 = unpack2(acc2[i][1]);
        float4 v;
        v.x = f0.x * inv; v.y = f0.y * inv;
        v.z = f1.x * inv; v.w = f1.y * inv;
        *(float4*)&g_attn[((size_t)b * S_ + srow) * EMB_ + h * HD_ + tx * 4] = v;
    }
}

// ---------------- launch ---------------------------------------------------
extern "C" void kernel_launch(void* const* d_in, const int* in_sizes, int n_in,
                              void* d_out, int out_size)
{
    const float* x  = (const float*)d_in[0];
    const float* Wq = (const float*)d_in[1];
    const float* bq = (const float*)d_in[2];
    const float* Wk = (const float*)d_in[3];
    const float* bk = (const float*)d_in[4];
    const float* Wv = (const float*)d_in[5];
    const float* bv = (const float*)d_in[6];
    const float* Wo = (const float*)d_in[7];
    const float* bo = (const float*)d_in[8];
    // d_in[9] = causal_mask (int32) — causality implemented analytically.
    float* out = (float*)d_out;

    cudaFuncSetAttribute(attn_kernel,
                         cudaFuncAttributeMaxDynamicSharedMemorySize, ATTN_SMEM);

    qkv_kernel<<<dim3(EMB_ / BN, M_ / BM, 3), 256>>>(x, Wq, bq, Wk, bk, Wv, bv);
    attn_kernel<<<dim3(S_ / AT, B_ * H_), 256, ATTN_SMEM>>>();
    oproj_kernel<<<dim3(EMB_ / BN, M_ / BM), 256>>>(Wo, bo, out);
}

// round 4
// speedup vs baseline: 1.6178x; 1.6178x over previous
#include <cuda_runtime.h>
#include <cuda_bf16.h>
#include <math.h>
#include <stdint.h>

#define B_   4
#define S_   2048
#define EMB_ 1024
#define H_   16
#define HD_  64
#define M_   (B_ * S_)   // 8192

typedef unsigned long long ull;
struct __align__(16) u64x2 { ull x, y; };

// ---- packed fp32x2 helpers (attention) ------------------------------------
__device__ __forceinline__ ull bcast2(float v) {
    ull r; asm("mov.b64 %0, {%1, %1};" : "=l"(r) : "f"(v)); return r;
}
__device__ __forceinline__ ull fma2(ull a, ull b, ull c) {
    ull d; asm("fma.rn.f32x2 %0, %1, %2, %3;" : "=l"(d) : "l"(a), "l"(b), "l"(c)); return d;
}
__device__ __forceinline__ ull mul2(ull a, ull b) {
    ull d; asm("mul.rn.f32x2 %0, %1, %2;" : "=l"(d) : "l"(a), "l"(b)); return d;
}
__device__ __forceinline__ float2 unpack2(ull v) {
    float2 f; asm("mov.b64 {%0, %1}, %2;" : "=f"(f.x), "=f"(f.y) : "l"(v)); return f;
}

// ---- ptx helpers (mma.sync / ldmatrix / cp.async) — baseline sm_103 legal --
__device__ __forceinline__ uint32_t smem_u32(const void* p) {
    uint32_t a;
    asm("{ .reg .u64 t; cvta.to.shared.u64 t, %1; cvt.u32.u64 %0, t; }"
        : "=r"(a) : "l"(p));
    return a;
}
__device__ __forceinline__ void cpa16(uint32_t dst, const void* src) {
    asm volatile("cp.async.cg.shared.global [%0], [%1], 16;" :: "r"(dst), "l"(src) : "memory");
}
#define CPA_COMMIT() asm volatile("cp.async.commit_group;" ::: "memory")
#define CPA_WAIT1()  asm volatile("cp.async.wait_group 1;"  ::: "memory")

#define LDSM4(r0, r1, r2, r3, addr) \
    asm volatile("ldmatrix.sync.aligned.m8n8.x4.shared.b16 {%0,%1,%2,%3}, [%4];" \
        : "=r"(r0), "=r"(r1), "=r"(r2), "=r"(r3) : "r"(addr))

#define MMA16816(c, a, b0, b1) \
    asm volatile("mma.sync.aligned.m16n8k16.row.col.f32.bf16.bf16.f32 " \
        "{%0,%1,%2,%3},{%4,%5,%6,%7},{%8,%9},{%0,%1,%2,%3};" \
        : "+f"((c)[0]), "+f"((c)[1]), "+f"((c)[2]), "+f"((c)[3]) \
        : "r"((a)[0]), "r"((a)[1]), "r"((a)[2]), "r"((a)[3]), "r"(b0), "r"(b1))

// ---------------- scratch (device globals; no allocation allowed) ----------
__device__ float g_q[(size_t)B_ * H_ * S_ * HD_];
__device__ float g_k[(size_t)B_ * H_ * S_ * HD_];
__device__ float g_v[(size_t)B_ * H_ * S_ * HD_];
__device__ __align__(16) __nv_bfloat16 g_xhi[(size_t)M_ * EMB_];
__device__ __align__(16) __nv_bfloat16 g_xlo[(size_t)M_ * EMB_];
__device__ __align__(16) __nv_bfloat16 g_whi[(size_t)4 * EMB_ * EMB_];
__device__ __align__(16) __nv_bfloat16 g_wlo[(size_t)4 * EMB_ * EMB_];
__device__ __align__(16) __nv_bfloat16 g_ahi[(size_t)M_ * EMB_];
__device__ __align__(16) __nv_bfloat16 g_alo[(size_t)M_ * EMB_];

// ---------------- fp32 -> bf16 hi/lo split ---------------------------------
// which: 0 -> x, 1..4 -> W[which-1]
__global__ __launch_bounds__(256) void conv_split_kernel(
    const float* __restrict__ src, int which, int n4)
{
    __nv_bfloat16 *hi, *lo;
    if (which == 0) { hi = g_xhi; lo = g_xlo; }
    else {
        hi = g_whi + (size_t)(which - 1) * EMB_ * EMB_;
        lo = g_wlo + (size_t)(which - 1) * EMB_ * EMB_;
    }
    int i = blockIdx.x * 256 + threadIdx.x;
    if (i >= n4) return;
    float4 v = ((const float4*)src)[i];
    __nv_bfloat16 h0 = __float2bfloat16(v.x), h1 = __float2bfloat16(v.y);
    __nv_bfloat16 h2 = __float2bfloat16(v.z), h3 = __float2bfloat16(v.w);
    __nv_bfloat16 l0 = __float2bfloat16(v.x - __bfloat162float(h0));
    __nv_bfloat16 l1 = __float2bfloat16(v.y - __bfloat162float(h1));
    __nv_bfloat16 l2 = __float2bfloat16(v.z - __bfloat162float(h2));
    __nv_bfloat16 l3 = __float2bfloat16(v.w - __bfloat162float(h3));
    ((__nv_bfloat162*)hi)[2 * i]     = __halves2bfloat162(h0, h1);
    ((__nv_bfloat162*)hi)[2 * i + 1] = __halves2bfloat162(h2, h3);
    ((__nv_bfloat162*)lo)[2 * i]     = __halves2bfloat162(l0, l1);
    ((__nv_bfloat162*)lo)[2 * i + 1] = __halves2bfloat162(l2, l3);
}

// ---------------- mma.sync GEMM: D = A @ W^T + bias -------------------------
// 3-term bf16 split: D = Ahi*Bhi + Ahi*Blo + Alo*Bhi (fp32 accum).
// CTA tile 128x128, K chunk 64, 2-stage cp.async double buffer.
// mode 0: A = x split, W = W[z], scatter into g_q/g_k/g_v as [B,H,S,hd]
// mode 1: A = attn split, W = W[3], write outp[m*EMB+n]
constexpr int GSTRIDE = 144;                       // padded row stride (bytes)
constexpr int GMAT    = 128 * GSTRIDE;             // 18432 per matrix
constexpr int GSTAGE  = 4 * GMAT;                  // 73728 per stage
constexpr int GEMM_SMEM = 2 * GSTAGE;              // 147456

__device__ __forceinline__ void gload_chunk(
    uint32_t sbase, const __nv_bfloat16* Ahi, const __nv_bfloat16* Alo,
    const __nv_bfloat16* Bhi, const __nv_bfloat16* Blo,
    int row0, int col0, int k0, int tid)
{
    #pragma unroll
    for (int i = tid; i < 4096; i += 256) {
        int mat = i >> 10;
        int r   = (i >> 3) & 127;
        int c   = i & 7;
        uint32_t dst = sbase + mat * GMAT + r * GSTRIDE + c * 16;
        const __nv_bfloat16* m =
            (mat == 0) ? Ahi : (mat == 1) ? Alo : (mat == 2) ? Bhi : Blo;
        int gr = ((mat < 2) ? row0 : col0) + r;
        cpa16(dst, m + (size_t)gr * EMB_ + k0 + c * 8);
    }
    CPA_COMMIT();
}

__global__ __launch_bounds__(256) void gemm_mma_kernel(
    const float* __restrict__ bq, const float* __restrict__ bk,
    const float* __restrict__ bv, float* __restrict__ outp, int mode)
{
    extern __shared__ char smem[];
    const uint32_t sb = smem_u32(smem);
    const int tid = threadIdx.x, wid = tid >> 5, lane = tid & 31;
    const int row0 = blockIdx.y * 128, col0 = blockIdx.x * 128;
    const int z = blockIdx.z;

    const __nv_bfloat16 *Ahi, *Alo, *Bhi, *Blo;
    const float* bias;
    if (mode == 0) {
        Ahi = g_xhi; Alo = g_xlo;
        Bhi = g_whi + (size_t)z * EMB_ * EMB_;
        Blo = g_wlo + (size_t)z * EMB_ * EMB_;
        bias = (z == 0) ? bq : (z == 1) ? bk : bv;
    } else {
        Ahi = g_ahi; Alo = g_alo;
        Bhi = g_whi + (size_t)3 * EMB_ * EMB_;
        Blo = g_wlo + (size_t)3 * EMB_ * EMB_;
        bias = bq;
    }

    const int wm = (wid & 1) * 64;       // warp M offset within tile
    const int wn = (wid >> 1) * 32;      // warp N offset within tile

    float c[4][4][4] = {};               // [mt][nt][reg]

    gload_chunk(sb,          Ahi, Alo, Bhi, Blo, row0, col0, 0,  tid);
    gload_chunk(sb + GSTAGE, Ahi, Alo, Bhi, Blo, row0, col0, 64, tid);

    // precomputed ldmatrix lane addressing (byte offsets within a matrix)
    const int a_row = wm + (lane & 7) + ((lane >> 3) & 1) * 8;  // + mt*16
    const int a_kc  = ((lane >> 4) & 1) * 8;                    // + kk
    const int b_row = wn + (lane & 7) + ((lane >> 4) & 1) * 8;  // + pt*16
    const int b_kc  = ((lane >> 3) & 1) * 8;                    // + kk

    for (int ch = 0; ch < 16; ++ch) {
        const int s = ch & 1;
        CPA_WAIT1();
        __syncthreads();
        const uint32_t st = sb + s * GSTAGE;

        #pragma unroll
        for (int kk = 0; kk < 64; kk += 16) {
            uint32_t bh[2][4], bl[2][4];
            #pragma unroll
            for (int pt = 0; pt < 2; ++pt) {
                uint32_t addr = st + 2 * GMAT + (b_row + pt * 16) * GSTRIDE
                              + (kk + b_kc) * 2;
                LDSM4(bh[pt][0], bh[pt][1], bh[pt][2], bh[pt][3], addr);
                LDSM4(bl[pt][0], bl[pt][1], bl[pt][2], bl[pt][3], addr + GMAT);
            }
            #pragma unroll
            for (int mt = 0; mt < 4; ++mt) {
                uint32_t addr = st + (a_row + mt * 16) * GSTRIDE
                              + (kk + a_kc) * 2;
                uint32_t ah[4], al[4];
                LDSM4(ah[0], ah[1], ah[2], ah[3], addr);
                LDSM4(al[0], al[1], al[2], al[3], addr + GMAT);
                #pragma unroll
                for (int nt = 0; nt < 4; ++nt) {
                    const int pt = nt >> 1, hf = (nt & 1) * 2;
                    MMA16816(c[mt][nt], ah, bh[pt][hf], bh[pt][hf + 1]);
                    MMA16816(c[mt][nt], ah, bl[pt][hf], bl[pt][hf + 1]);
                    MMA16816(c[mt][nt], al, bh[pt][hf], bh[pt][hf + 1]);
                }
            }
        }
        __syncthreads();
        if (ch + 2 < 16)
            gload_chunk(sb + s * GSTAGE, Ahi, Alo, Bhi, Blo,
                        row0, col0, (ch + 2) * 64, tid);
        else
            CPA_COMMIT();  // keep group count in lockstep for CPA_WAIT1
    }

    // Epilogue: c-frag thread mapping: rows (l/4, l/4+8), cols (l%4)*2,+1
    #pragma unroll
    for (int mt = 0; mt < 4; ++mt) {
        #pragma unroll
        for (int nt = 0; nt < 4; ++nt) {
            int r = row0 + wm + mt * 16 + (lane >> 2);
            int n = col0 + wn + nt * 8 + (lane & 3) * 2;
            float2 bv2 = *(const float2*)&bias[n];
            float2 v0, v1;
            v0.x = c[mt][nt][0] + bv2.x; v0.y = c[mt][nt][1] + bv2.y;
            v1.x = c[mt][nt][2] + bv2.x; v1.y = c[mt][nt][3] + bv2.y;
            if (mode == 0) {
                float* outsel = (z == 0) ? g_q : (z == 1) ? g_k : g_v;
                int h = n >> 6, d = n & 63;
                int bb0 = r >> 11, s0 = r & 2047;
                int bb1 = (r + 8) >> 11, s1 = (r + 8) & 2047;
                *(float2*)&outsel[(((size_t)bb0 * H_ + h) * S_ + s0) * HD_ + d] = v0;
                *(float2*)&outsel[(((size_t)bb1 * H_ + h) * S_ + s1) * HD_ + d] = v1;
            } else {
                *(float2*)&outp[(size_t)r * EMB_ + n] = v0;
                *(float2*)&outp[(size_t)(r + 8) * EMB_ + n] = v1;
            }
        }
    }
}

// ---------------- causal flash attention (fp32x2, online softmax) ----------
constexpr int AT   = 64;
constexpr int APAD = 68;
constexpr int ATTN_SMEM = 4 * AT * APAD * (int)sizeof(float);  // 69632 B

__global__ __launch_bounds__(256) void attn_kernel()
{
    extern __shared__ float sm[];
    float (*Qs)[APAD] = (float(*)[APAD])(sm);
    float (*Kt)[APAD] = (float(*)[APAD])(sm + 1 * AT * APAD);
    float (*Vs)[APAD] = (float(*)[APAD])(sm + 2 * AT * APAD);
    float (*Ps)[APAD] = (float(*)[APAD])(sm + 3 * AT * APAD);

    const int qt = blockIdx.x;
    const int bh = blockIdx.y;
    const float* Qg = g_q + (size_t)bh * S_ * HD_;
    const float* Kg = g_k + (size_t)bh * S_ * HD_;
    const float* Vg = g_v + (size_t)bh * S_ * HD_;

    const int t  = threadIdx.x;
    const int tx = t & 15;
    const int ty = t >> 4;

    #pragma unroll
    for (int r = 0; r < 4; ++r) {
        int id  = t + r * 256;
        int row = id >> 4;
        int c4  = (id & 15) * 4;
        *(float4*)&Qs[row][c4] =
            *(const float4*)&Qg[(size_t)(qt * AT + row) * HD_ + c4];
    }

    float m[4], l[4];
    ull acc2[4][2];
    #pragma unroll
    for (int i = 0; i < 4; ++i) {
        m[i] = -1e30f; l[i] = 0.0f;
        acc2[i][0] = 0ull; acc2[i][1] = 0ull;
    }
    const float scale = 0.125f;

    for (int kt = 0; kt <= qt; ++kt) {
        __syncthreads();
        #pragma unroll
        for (int r = 0; r < 4; ++r) {
            int id  = t + r * 256;
            int row = id >> 4;
            int c4  = (id & 15) * 4;
            float4 kv = *(const float4*)&Kg[(size_t)(kt * AT + row) * HD_ + c4];
            Kt[c4 + 0][row] = kv.x; Kt[c4 + 1][row] = kv.y;
            Kt[c4 + 2][row] = kv.z; Kt[c4 + 3][row] = kv.w;
            *(float4*)&Vs[row][c4] =
                *(const float4*)&Vg[(size_t)(kt * AT + row) * HD_ + c4];
        }
        __syncthreads();

        ull s2[4][2] = {};
        #pragma unroll
        for (int d4 = 0; d4 < 16; ++d4) {
            float4 q4[4];
            #pragma unroll
            for (int i = 0; i < 4; ++i)
                q4[i] = *(const float4*)&Qs[ty * 4 + i][d4 * 4];
            #pragma unroll
            for (int dd = 0; dd < 4; ++dd) {
                u64x2 k2 = *(const u64x2*)&Kt[d4 * 4 + dd][tx * 4];
                #pragma unroll
                for (int i = 0; i < 4; ++i) {
                    ull qv = bcast2(((const float*)&q4[i])[dd]);
                    s2[i][0] = fma2(qv, k2.x, s2[i][0]);
                    s2[i][1] = fma2(qv, k2.y, s2[i][1]);
                }
            }
        }

        float s[4][4];
        const bool diag = (kt == qt);
        #pragma unroll
        for (int i = 0; i < 4; ++i) {
            int li = ty * 4 + i;
            float2 f0 = unpack2(s2[i][0]);
            float2 f1 = unpack2(s2[i][1]);
            s[i][0] = f0.x * scale; s[i][1] = f0.y * scale;
            s[i][2] = f1.x * scale; s[i][3] = f1.y * scale;
            if (diag) {
                #pragma unroll
                for (int j = 0; j < 4; ++j)
                    if ((tx * 4 + j) > li) s[i][j] = -1e30f;
            }
        }

        #pragma unroll
        for (int i = 0; i < 4; ++i) {
            float mx = fmaxf(fmaxf(s[i][0], s[i][1]), fmaxf(s[i][2], s[i][3]));
            #pragma unroll
            for (int o = 8; o >= 1; o >>= 1)
                mx = fmaxf(mx, __shfl_xor_sync(0xffffffffu, mx, o));
            float newm = fmaxf(m[i], mx);
            float f    = __expf(m[i] - newm);
            float psum = 0.0f;
            #pragma unroll
            for (int j = 0; j < 4; ++j) {
                float p = __expf(s[i][j] - newm);
                s[i][j] = p;
                psum += p;
            }
            #pragma unroll
            for (int o = 8; o >= 1; o >>= 1)
                psum += __shfl_xor_sync(0xffffffffu, psum, o);
            l[i] = l[i] * f + psum;
            m[i] = newm;
            ull fp = bcast2(f);
            acc2[i][0] = mul2(acc2[i][0], fp);
            acc2[i][1] = mul2(acc2[i][1], fp);
            *(float4*)&Ps[ty * 4 + i][tx * 4] = *(float4*)&s[i][0];
        }
        __syncthreads();

        #pragma unroll
        for (int k4 = 0; k4 < 16; ++k4) {
            float4 p4[4];
            #pragma unroll
            for (int i = 0; i < 4; ++i)
                p4[i] = *(const float4*)&Ps[ty * 4 + i][k4 * 4];
            #pragma unroll
            for (int kk = 0; kk < 4; ++kk) {
                u64x2 v2 = *(const u64x2*)&Vs[k4 * 4 + kk][tx * 4];
                #pragma unroll
                for (int i = 0; i < 4; ++i) {
                    ull pv = bcast2(((const float*)&p4[i])[kk]);
                    acc2[i][0] = fma2(pv, v2.x, acc2[i][0]);
                    acc2[i][1] = fma2(pv, v2.y, acc2[i][1]);
                }
            }
        }
    }

    // Epilogue: normalize + split to bf16 hi/lo for the mma.sync oproj
    const int b = bh / H_, h = bh % H_;
    #pragma unroll
    for (int i = 0; i < 4; ++i) {
        float inv = 1.0f / l[i];
        int srow  = qt * AT + ty * 4 + i;
        float2 f0 = unpack2(acc2[i][0]);
        float2 f1 = unpack2(acc2[i][1]);
        float v0 = f0.x * inv, v1 = f0.y * inv, v2 = f1.x * inv, v3 = f1.y * inv;
        size_t idx = ((size_t)b * S_ + srow) * EMB_ + h * HD_ + tx * 4;
        __nv_bfloat16 h0 = __float2bfloat16(v0), h1 = __float2bfloat16(v1);
        __nv_bfloat16 h2 = __float2bfloat16(v2), h3 = __float2bfloat16(v3);
        *(__nv_bfloat162*)&g_ahi[idx]     = __halves2bfloat162(h0, h1);
        *(__nv_bfloat162*)&g_ahi[idx + 2] = __halves2bfloat162(h2, h3);
        __nv_bfloat16 l0 = __float2bfloat16(v0 - __bfloat162float(h0));
        __nv_bfloat16 l1 = __float2bfloat16(v1 - __bfloat162float(h1));
        __nv_bfloat16 l2 = __float2bfloat16(v2 - __bfloat162float(h2));
        __nv_bfloat16 l3 = __float2bfloat16(v3 - __bfloat162float(h3));
        *(__nv_bfloat162*)&g_alo[idx]     = __halves2bfloat162(l0, l1);
        *(__nv_bfloat162*)&g_alo[idx + 2] = __halves2bfloat162(l2, l3);
    }
}

// ---------------- launch ---------------------------------------------------
extern "C" void kernel_launch(void* const* d_in, const int* in_sizes, int n_in,
                              void* d_out, int out_size)
{
    const float* x  = (const float*)d_in[0];
    const float* Wq = (const float*)d_in[1];
    const float* bq = (const float*)d_in[2];
    const float* Wk = (const float*)d_in[3];
    const float* bk = (const float*)d_in[4];
    const float* Wv = (const float*)d_in[5];
    const float* bv = (const float*)d_in[6];
    const float* Wo = (const float*)d_in[7];
    const float* bo = (const float*)d_in[8];
    float* out = (float*)d_out;

    cudaFuncSetAttribute(attn_kernel,
                         cudaFuncAttributeMaxDynamicSharedMemorySize, ATTN_SMEM);
    cudaFuncSetAttribute(gemm_mma_kernel,
                         cudaFuncAttributeMaxDynamicSharedMemorySize, GEMM_SMEM);

    const int n4x = M_ * EMB_ / 4;
    const int n4w = EMB_ * EMB_ / 4;
    conv_split_kernel<<<n4x / 256, 256>>>(x,  0, n4x);
    conv_split_kernel<<<n4w / 256, 256>>>(Wq, 1, n4w);
    conv_split_kernel<<<n4w / 256, 256>>>(Wk, 2, n4w);
    conv_split_kernel<<<n4w / 256, 256>>>(Wv, 3, n4w);
    conv_split_kernel<<<n4w / 256, 256>>>(Wo, 4, n4w);

    // QKV projections (tensor cores via mma.sync)
    gemm_mma_kernel<<<dim3(EMB_ / 128, M_ / 128, 3), 256, GEMM_SMEM>>>(
        bq, bk, bv, nullptr, 0);

    // causal attention (SIMT)
    attn_kernel<<<dim3(S_ / AT, B_ * H_), 256, ATTN_SMEM>>>();

    // output projection (tensor cores via mma.sync)
    gemm_mma_kernel<<<dim3(EMB_ / 128, M_ / 128, 1), 256, GEMM_SMEM>>>(
        bo, nullptr, nullptr, out, 1);
}

// round 5
// speedup vs baseline: 2.8108x; 1.7373x over previous
#include <cuda_runtime.h>
#include <cuda_bf16.h>
#include <math.h>
#include <stdint.h>

#define B_   4
#define S_   2048
#define EMB_ 1024
#define H_   16
#define HD_  64
#define M_   (B_ * S_)   // 8192

// ---- ptx helpers (mma.sync / ldmatrix / cp.async) — baseline sm_103 legal --
__device__ __forceinline__ uint32_t smem_u32(const void* p) {
    uint32_t a;
    asm("{ .reg .u64 t; cvta.to.shared.u64 t, %1; cvt.u32.u64 %0, t; }"
        : "=r"(a) : "l"(p));
    return a;
}
__device__ __forceinline__ void cpa16(uint32_t dst, const void* src) {
    asm volatile("cp.async.cg.shared.global [%0], [%1], 16;" :: "r"(dst), "l"(src) : "memory");
}
#define CPA_COMMIT() asm volatile("cp.async.commit_group;" ::: "memory")
#define CPA_WAIT1()  asm volatile("cp.async.wait_group 1;"  ::: "memory")

#define LDSM4(r0, r1, r2, r3, addr) \
    asm volatile("ldmatrix.sync.aligned.m8n8.x4.shared.b16 {%0,%1,%2,%3}, [%4];" \
        : "=r"(r0), "=r"(r1), "=r"(r2), "=r"(r3) : "r"(addr))
#define LDSM4T(r0, r1, r2, r3, addr) \
    asm volatile("ldmatrix.sync.aligned.m8n8.x4.trans.shared.b16 {%0,%1,%2,%3}, [%4];" \
        : "=r"(r0), "=r"(r1), "=r"(r2), "=r"(r3) : "r"(addr))

#define MMA16816(c, a, b0, b1) \
    asm volatile("mma.sync.aligned.m16n8k16.row.col.f32.bf16.bf16.f32 " \
        "{%0,%1,%2,%3},{%4,%5,%6,%7},{%8,%9},{%0,%1,%2,%3};" \
        : "+f"((c)[0]), "+f"((c)[1]), "+f"((c)[2]), "+f"((c)[3]) \
        : "r"((a)[0]), "r"((a)[1]), "r"((a)[2]), "r"((a)[3]), "r"(b0), "r"(b1))

__device__ __forceinline__ uint32_t packbf(float lo, float hi) {
    uint32_t r;
    asm("cvt.rn.bf16x2.f32 %0, %1, %2;" : "=r"(r) : "f"(hi), "f"(lo));
    return r;
}
__device__ __forceinline__ float bflo(uint32_t p) { return __uint_as_float(p << 16); }
__device__ __forceinline__ float bfhi(uint32_t p) { return __uint_as_float(p & 0xffff0000u); }
__device__ __forceinline__ float ex2(float x) {
    float r; asm("ex2.approx.f32 %0, %1;" : "=f"(r) : "f"(x)); return r;
}

// ---------------- scratch (device globals; no allocation allowed) ----------
__device__ __align__(16) __nv_bfloat16 g_xhi[(size_t)M_ * EMB_];
__device__ __align__(16) __nv_bfloat16 g_xlo[(size_t)M_ * EMB_];
__device__ __align__(16) __nv_bfloat16 g_whi[(size_t)4 * EMB_ * EMB_];
__device__ __align__(16) __nv_bfloat16 g_wlo[(size_t)4 * EMB_ * EMB_];
__device__ __align__(16) __nv_bfloat16 g_qhi[(size_t)M_ * EMB_];
__device__ __align__(16) __nv_bfloat16 g_qlo[(size_t)M_ * EMB_];
__device__ __align__(16) __nv_bfloat16 g_khi[(size_t)M_ * EMB_];
__device__ __align__(16) __nv_bfloat16 g_klo[(size_t)M_ * EMB_];
__device__ __align__(16) __nv_bfloat16 g_vhi[(size_t)M_ * EMB_];
__device__ __align__(16) __nv_bfloat16 g_vlo[(size_t)M_ * EMB_];
__device__ __align__(16) __nv_bfloat16 g_ahi[(size_t)M_ * EMB_];
__device__ __align__(16) __nv_bfloat16 g_alo[(size_t)M_ * EMB_];

// ---------------- fp32 -> bf16 hi/lo split (x, weights) --------------------
__global__ __launch_bounds__(256) void conv_split_kernel(
    const float* __restrict__ src, int which, int n4)
{
    __nv_bfloat16 *hi, *lo;
    if (which == 0) { hi = g_xhi; lo = g_xlo; }
    else {
        hi = g_whi + (size_t)(which - 1) * EMB_ * EMB_;
        lo = g_wlo + (size_t)(which - 1) * EMB_ * EMB_;
    }
    int i = blockIdx.x * 256 + threadIdx.x;
    if (i >= n4) return;
    float4 v = ((const float4*)src)[i];
    uint32_t h01 = packbf(v.x, v.y), h23 = packbf(v.z, v.w);
    uint32_t l01 = packbf(v.x - bflo(h01), v.y - bfhi(h01));
    uint32_t l23 = packbf(v.z - bflo(h23), v.w - bfhi(h23));
    ((uint32_t*)hi)[2 * i] = h01; ((uint32_t*)hi)[2 * i + 1] = h23;
    ((uint32_t*)lo)[2 * i] = l01; ((uint32_t*)lo)[2 * i + 1] = l23;
}

// ---------------- mma.sync GEMM: D = A @ W^T + bias -------------------------
constexpr int GSTRIDE = 144;
constexpr int GMAT    = 128 * GSTRIDE;             // 18432
constexpr int GSTAGE  = 4 * GMAT;                  // 73728
constexpr int GEMM_SMEM = 2 * GSTAGE;              // 147456

__device__ __forceinline__ void gload_chunk(
    uint32_t sbase, const __nv_bfloat16* Ahi, const __nv_bfloat16* Alo,
    const __nv_bfloat16* Bhi, const __nv_bfloat16* Blo,
    int row0, int col0, int k0, int tid)
{
    #pragma unroll
    for (int i = tid; i < 4096; i += 256) {
        int mat = i >> 10;
        int r   = (i >> 3) & 127;
        int c   = i & 7;
        uint32_t dst = sbase + mat * GMAT + r * GSTRIDE + c * 16;
        const __nv_bfloat16* m =
            (mat == 0) ? Ahi : (mat == 1) ? Alo : (mat == 2) ? Bhi : Blo;
        int gr = ((mat < 2) ? row0 : col0) + r;
        cpa16(dst, m + (size_t)gr * EMB_ + k0 + c * 8);
    }
    CPA_COMMIT();
}

// mode 0: A = x split, W = W[z]; write bf16 hi/lo Q/K/V in [B,H,S,hd]
// mode 1: A = attn split, W = W[3]; write fp32 outp[m*EMB+n]
__global__ __launch_bounds__(256) void gemm_mma_kernel(
    const float* __restrict__ bq, const float* __restrict__ bk,
    const float* __restrict__ bv, float* __restrict__ outp, int mode)
{
    extern __shared__ char smem[];
    const uint32_t sb = smem_u32(smem);
    const int tid = threadIdx.x, wid = tid >> 5, lane = tid & 31;
    const int row0 = blockIdx.y * 128, col0 = blockIdx.x * 128;
    const int z = blockIdx.z;

    const __nv_bfloat16 *Ahi, *Alo, *Bhi, *Blo;
    const float* bias;
    if (mode == 0) {
        Ahi = g_xhi; Alo = g_xlo;
        Bhi = g_whi + (size_t)z * EMB_ * EMB_;
        Blo = g_wlo + (size_t)z * EMB_ * EMB_;
        bias = (z == 0) ? bq : (z == 1) ? bk : bv;
    } else {
        Ahi = g_ahi; Alo = g_alo;
        Bhi = g_whi + (size_t)3 * EMB_ * EMB_;
        Blo = g_wlo + (size_t)3 * EMB_ * EMB_;
        bias = bq;
    }

    const int wm = (wid & 1) * 64;
    const int wn = (wid >> 1) * 32;

    float c[4][4][4] = {};

    gload_chunk(sb,          Ahi, Alo, Bhi, Blo, row0, col0, 0,  tid);
    gload_chunk(sb + GSTAGE, Ahi, Alo, Bhi, Blo, row0, col0, 64, tid);

    const int a_row = wm + (lane & 7) + ((lane >> 3) & 1) * 8;
    const int a_kc  = ((lane >> 4) & 1) * 8;
    const int b_row = wn + (lane & 7) + ((lane >> 4) & 1) * 8;
    const int b_kc  = ((lane >> 3) & 1) * 8;

    for (int ch = 0; ch < 16; ++ch) {
        const int s = ch & 1;
        CPA_WAIT1();
        __syncthreads();
        const uint32_t st = sb + s * GSTAGE;

        #pragma unroll
        for (int kk = 0; kk < 64; kk += 16) {
            uint32_t bh[2][4], bl[2][4];
            #pragma unroll
            for (int pt = 0; pt < 2; ++pt) {
                uint32_t addr = st + 2 * GMAT + (b_row + pt * 16) * GSTRIDE
                              + (kk + b_kc) * 2;
                LDSM4(bh[pt][0], bh[pt][1], bh[pt][2], bh[pt][3], addr);
                LDSM4(bl[pt][0], bl[pt][1], bl[pt][2], bl[pt][3], addr + GMAT);
            }
            #pragma unroll
            for (int mt = 0; mt < 4; ++mt) {
                uint32_t addr = st + (a_row + mt * 16) * GSTRIDE
                              + (kk + a_kc) * 2;
                uint32_t ah[4], al[4];
                LDSM4(ah[0], ah[1], ah[2], ah[3], addr);
                LDSM4(al[0], al[1], al[2], al[3], addr + GMAT);
                #pragma unroll
                for (int nt = 0; nt < 4; ++nt) {
                    const int pt = nt >> 1, hf = (nt & 1) * 2;
                    MMA16816(c[mt][nt], ah, bh[pt][hf], bh[pt][hf + 1]);
                    MMA16816(c[mt][nt], ah, bl[pt][hf], bl[pt][hf + 1]);
                    MMA16816(c[mt][nt], al, bh[pt][hf], bh[pt][hf + 1]);
                }
            }
        }
        __syncthreads();
        if (ch + 2 < 16)
            gload_chunk(sb + s * GSTAGE, Ahi, Alo, Bhi, Blo,
                        row0, col0, (ch + 2) * 64, tid);
        else
            CPA_COMMIT();
    }

    #pragma unroll
    for (int mt = 0; mt < 4; ++mt) {
        #pragma unroll
        for (int nt = 0; nt < 4; ++nt) {
            int r = row0 + wm + mt * 16 + (lane >> 2);
            int n = col0 + wn + nt * 8 + (lane & 3) * 2;
            float2 bv2 = *(const float2*)&bias[n];
            float p0 = c[mt][nt][0] + bv2.x, p1 = c[mt][nt][1] + bv2.y;
            float p2 = c[mt][nt][2] + bv2.x, p3 = c[mt][nt][3] + bv2.y;
            if (mode == 0) {
                __nv_bfloat16 *dh, *dl;
                if (z == 0)      { dh = g_qhi; dl = g_qlo; }
                else if (z == 1) { dh = g_khi; dl = g_klo; }
                else             { dh = g_vhi; dl = g_vlo; }
                int h = n >> 6, d = n & 63;
                int bb0 = r >> 11, s0 = r & 2047;
                int bb1 = (r + 8) >> 11, s1 = (r + 8) & 2047;
                size_t i0 = (((size_t)bb0 * H_ + h) * S_ + s0) * HD_ + d;
                size_t i1 = (((size_t)bb1 * H_ + h) * S_ + s1) * HD_ + d;
                uint32_t h01 = packbf(p0, p1);
                uint32_t l01 = packbf(p0 - bflo(h01), p1 - bfhi(h01));
                uint32_t h23 = packbf(p2, p3);
                uint32_t l23 = packbf(p2 - bflo(h23), p3 - bfhi(h23));
                *(uint32_t*)&dh[i0] = h01; *(uint32_t*)&dl[i0] = l01;
                *(uint32_t*)&dh[i1] = h23; *(uint32_t*)&dl[i1] = l23;
            } else {
                float2 v0 = {p0, p1}, v1 = {p2, p3};
                *(float2*)&outp[(size_t)r * EMB_ + n] = v0;
                *(float2*)&outp[(size_t)(r + 8) * EMB_ + n] = v1;
            }
        }
    }
}

// ---------------- mma.sync causal flash attention ---------------------------
// CTA: 128 q-rows x (64-key k-tiles), 8 warps x 16 q-rows, bf16 3-term split.
constexpr int ASTR  = 144;                  // smem row stride (bytes)
constexpr int AQMAT = 128 * ASTR;           // 18432 (Q hi or lo)
constexpr int AKMAT = 64 * ASTR;            // 9216  (K/V hi or lo)
constexpr int ASTAGE = 4 * AKMAT;           // 36864 (Khi,Klo,Vhi,Vlo)
constexpr int ATTN_SMEM = 2 * AQMAT + 2 * ASTAGE;   // 110592

__device__ __forceinline__ void akv_load(
    uint32_t base, const __nv_bfloat16* Kh, const __nv_bfloat16* Kl,
    const __nv_bfloat16* Vh, const __nv_bfloat16* Vl, int kt, int tid)
{
    #pragma unroll
    for (int i = tid; i < 2048; i += 256) {
        int mat = i >> 9;
        int r   = (i >> 3) & 63;
        int c   = i & 7;
        const __nv_bfloat16* m =
            (mat == 0) ? Kh : (mat == 1) ? Kl : (mat == 2) ? Vh : Vl;
        cpa16(base + mat * AKMAT + r * ASTR + c * 16,
              m + (size_t)(kt * 64 + r) * HD_ + c * 8);
    }
}

__global__ __launch_bounds__(256) void attn_mma_kernel()
{
    extern __shared__ char smem[];
    const uint32_t sb = smem_u32(smem);
    const int tid = threadIdx.x, wid = tid >> 5, lane = tid & 31;
    const int qt = blockIdx.x, bh = blockIdx.y;
    const size_t off = (size_t)bh * S_ * HD_;
    const __nv_bfloat16 *Qh = g_qhi + off, *Ql = g_qlo + off;
    const __nv_bfloat16 *Kh = g_khi + off, *Kl = g_klo + off;
    const __nv_bfloat16 *Vh = g_vhi + off, *Vl = g_vlo + off;
    const int ntiles = 2 * qt + 2;

    // prologue: Q (both mats) + KV stage 0 -> group 0; KV stage 1 -> group 1
    #pragma unroll
    for (int i = tid; i < 2048; i += 256) {
        int mat = i >> 10, r = (i >> 3) & 127, c = i & 7;
        const __nv_bfloat16* m = mat ? Ql : Qh;
        cpa16(sb + mat * AQMAT + r * ASTR + c * 16,
              m + (size_t)(qt * 128 + r) * HD_ + c * 8);
    }
    akv_load(sb + 2 * AQMAT, Kh, Kl, Vh, Vl, 0, tid);
    CPA_COMMIT();
    akv_load(sb + 2 * AQMAT + ASTAGE, Kh, Kl, Vh, Vl, 1, tid);
    CPA_COMMIT();

    // fragment addressing
    const int a_row = wid * 16 + (lane & 7) + ((lane >> 3) & 1) * 8;
    const int a_kc2 = ((lane >> 4) & 1) * 16;          // bytes
    const int b_row = (lane & 7) + ((lane >> 4) & 1) * 8;
    const int b_kc2 = ((lane >> 3) & 1) * 16;
    const int v_row = (lane & 7) + ((lane >> 3) & 1) * 8;
    const int v_cc2 = ((lane >> 4) & 1) * 16;
    const int row0g = qt * 128 + wid * 16 + (lane >> 2);

    float O[8][4] = {};
    float m0 = -1e30f, m1 = -1e30f, l0 = 0.0f, l1 = 0.0f;
    const float sc = 0.125f * 1.44269504f;   // scale * log2(e)

    for (int kt = 0; kt < ntiles; ++kt) {
        CPA_WAIT1();
        __syncthreads();
        const uint32_t st = sb + 2 * AQMAT + (kt & 1) * ASTAGE;

        // ---- S = Q K^T (3-term split, fp32 accum) ----
        float S[8][4] = {};
        #pragma unroll
        for (int ks = 0; ks < 4; ++ks) {
            uint32_t qaddr = sb + a_row * ASTR + ks * 32 + a_kc2;
            uint32_t ah[4], al[4];
            LDSM4(ah[0], ah[1], ah[2], ah[3], qaddr);
            LDSM4(al[0], al[1], al[2], al[3], qaddr + AQMAT);
            #pragma unroll
            for (int g = 0; g < 4; ++g) {
                uint32_t kaddr = st + (g * 16 + b_row) * ASTR + ks * 32 + b_kc2;
                uint32_t kh[4], kl[4];
                LDSM4(kh[0], kh[1], kh[2], kh[3], kaddr);
                LDSM4(kl[0], kl[1], kl[2], kl[3], kaddr + AKMAT);
                MMA16816(S[2 * g],     ah, kh[0], kh[1]);
                MMA16816(S[2 * g],     ah, kl[0], kl[1]);
                MMA16816(S[2 * g],     al, kh[0], kh[1]);
                MMA16816(S[2 * g + 1], ah, kh[2], kh[3]);
                MMA16816(S[2 * g + 1], ah, kl[2], kl[3]);
                MMA16816(S[2 * g + 1], al, kh[2], kh[3]);
            }
        }

        // ---- scale into log2 domain + causal mask ----
        #pragma unroll
        for (int j = 0; j < 8; ++j) {
            S[j][0] *= sc; S[j][1] *= sc; S[j][2] *= sc; S[j][3] *= sc;
        }
        if (kt * 64 + 63 > qt * 128 + wid * 16) {
            #pragma unroll
            for (int j = 0; j < 8; ++j) {
                int col = kt * 64 + j * 8 + (lane & 3) * 2;
                if (col     > row0g)     S[j][0] = -1e30f;
                if (col + 1 > row0g)     S[j][1] = -1e30f;
                if (col     > row0g + 8) S[j][2] = -1e30f;
                if (col + 1 > row0g + 8) S[j][3] = -1e30f;
            }
        }

        // ---- online softmax (rows spread over lane&3 quad) ----
        float mx0 = -1e30f, mx1 = -1e30f;
        #pragma unroll
        for (int j = 0; j < 8; ++j) {
            mx0 = fmaxf(mx0, fmaxf(S[j][0], S[j][1]));
            mx1 = fmaxf(mx1, fmaxf(S[j][2], S[j][3]));
        }
        mx0 = fmaxf(mx0, __shfl_xor_sync(0xffffffffu, mx0, 1));
        mx0 = fmaxf(mx0, __shfl_xor_sync(0xffffffffu, mx0, 2));
        mx1 = fmaxf(mx1, __shfl_xor_sync(0xffffffffu, mx1, 1));
        mx1 = fmaxf(mx1, __shfl_xor_sync(0xffffffffu, mx1, 2));
        float nm0 = fmaxf(m0, mx0), nm1 = fmaxf(m1, mx1);
        float f0 = ex2(m0 - nm0), f1 = ex2(m1 - nm1);
        m0 = nm0; m1 = nm1;
        float s0 = 0.0f, s1 = 0.0f;
        #pragma unroll
        for (int j = 0; j < 8; ++j) {
            S[j][0] = ex2(S[j][0] - nm0); S[j][1] = ex2(S[j][1] - nm0);
            S[j][2] = ex2(S[j][2] - nm1); S[j][3] = ex2(S[j][3] - nm1);
            s0 += S[j][0] + S[j][1];
            s1 += S[j][2] + S[j][3];
        }
        s0 += __shfl_xor_sync(0xffffffffu, s0, 1);
        s0 += __shfl_xor_sync(0xffffffffu, s0, 2);
        s1 += __shfl_xor_sync(0xffffffffu, s1, 1);
        s1 += __shfl_xor_sync(0xffffffffu, s1, 2);
        l0 = l0 * f0 + s0; l1 = l1 * f1 + s1;
        #pragma unroll
        for (int j = 0; j < 8; ++j) {
            O[j][0] *= f0; O[j][1] *= f0; O[j][2] *= f1; O[j][3] *= f1;
        }

        // ---- O += P V (P from registers, 3-term split) ----
        #pragma unroll
        for (int ks = 0; ks < 4; ++ks) {
            uint32_t ph[4], pl[4];
            ph[0] = packbf(S[2 * ks][0],     S[2 * ks][1]);
            ph[1] = packbf(S[2 * ks][2],     S[2 * ks][3]);
            ph[2] = packbf(S[2 * ks + 1][0], S[2 * ks + 1][1]);
            ph[3] = packbf(S[2 * ks + 1][2], S[2 * ks + 1][3]);
            pl[0] = packbf(S[2 * ks][0]     - bflo(ph[0]), S[2 * ks][1]     - bfhi(ph[0]));
            pl[1] = packbf(S[2 * ks][2]     - bflo(ph[1]), S[2 * ks][3]     - bfhi(ph[1]));
            pl[2] = packbf(S[2 * ks + 1][0] - bflo(ph[2]), S[2 * ks + 1][1] - bfhi(ph[2]));
            pl[3] = packbf(S[2 * ks + 1][2] - bflo(ph[3]), S[2 * ks + 1][3] - bfhi(ph[3]));
            #pragma unroll
            for (int g = 0; g < 4; ++g) {
                uint32_t vaddr = st + 2 * AKMAT + (ks * 16 + v_row) * ASTR
                               + g * 32 + v_cc2;
                uint32_t vh[4], vl[4];
                LDSM4T(vh[0], vh[1], vh[2], vh[3], vaddr);
                LDSM4T(vl[0], vl[1], vl[2], vl[3], vaddr + AKMAT);
                MMA16816(O[2 * g],     ph, vh[0], vh[1]);
                MMA16816(O[2 * g],     ph, vl[0], vl[1]);
                MMA16816(O[2 * g],     pl, vh[0], vh[1]);
                MMA16816(O[2 * g + 1], ph, vh[2], vh[3]);
                MMA16816(O[2 * g + 1], ph, vl[2], vl[3]);
                MMA16816(O[2 * g + 1], pl, vh[2], vh[3]);
            }
        }

        __syncthreads();
        if (kt + 2 < ntiles) {
            akv_load(sb + 2 * AQMAT + (kt & 1) * ASTAGE, Kh, Kl, Vh, Vl, kt + 2, tid);
            CPA_COMMIT();
        } else {
            CPA_COMMIT();
        }
    }

    // ---- epilogue: normalize, split bf16 hi/lo, write [B,S,EMB] ----
    const float inv0 = 1.0f / l0, inv1 = 1.0f / l1;
    const int b = bh >> 4, h = bh & 15;
    const int r0 = qt * 128 + wid * 16 + (lane >> 2);
    const int cc = (lane & 3) * 2;
    #pragma unroll
    for (int j = 0; j < 8; ++j) {
        float p0 = O[j][0] * inv0, p1 = O[j][1] * inv0;
        float p2 = O[j][2] * inv1, p3 = O[j][3] * inv1;
        size_t i0 = ((size_t)b * S_ + r0) * EMB_ + h * 64 + j * 8 + cc;
        size_t i1 = i0 + (size_t)8 * EMB_;
        uint32_t h01 = packbf(p0, p1);
        uint32_t l01 = packbf(p0 - bflo(h01), p1 - bfhi(h01));
        uint32_t h23 = packbf(p2, p3);
        uint32_t l23 = packbf(p2 - bflo(h23), p3 - bfhi(h23));
        *(uint32_t*)&g_ahi[i0] = h01; *(uint32_t*)&g_alo[i0] = l01;
        *(uint32_t*)&g_ahi[i1] = h23; *(uint32_t*)&g_alo[i1] = l23;
    }
}

// ---------------- launch ---------------------------------------------------
extern "C" void kernel_launch(void* const* d_in, const int* in_sizes, int n_in,
                              void* d_out, int out_size)
{
    const float* x  = (const float*)d_in[0];
    const float* Wq = (const float*)d_in[1];
    const float* bq = (const float*)d_in[2];
    const float* Wk = (const float*)d_in[3];
    const float* bk = (const float*)d_in[4];
    const float* Wv = (const float*)d_in[5];
    const float* bv = (const float*)d_in[6];
    const float* Wo = (const float*)d_in[7];
    const float* bo = (const float*)d_in[8];
    float* out = (float*)d_out;

    cudaFuncSetAttribute(gemm_mma_kernel,
                         cudaFuncAttributeMaxDynamicSharedMemorySize, GEMM_SMEM);
    cudaFuncSetAttribute(attn_mma_kernel,
                         cudaFuncAttributeMaxDynamicSharedMemorySize, ATTN_SMEM);

    const int n4x = M_ * EMB_ / 4;
    const int n4w = EMB_ * EMB_ / 4;
    conv_split_kernel<<<n4x / 256, 256>>>(x,  0, n4x);
    conv_split_kernel<<<n4w / 256, 256>>>(Wq, 1, n4w);
    conv_split_kernel<<<n4w / 256, 256>>>(Wk, 2, n4w);
    conv_split_kernel<<<n4w / 256, 256>>>(Wv, 3, n4w);
    conv_split_kernel<<<n4w / 256, 256>>>(Wo, 4, n4w);

    // QKV projections (mma.sync) -> bf16 hi/lo Q/K/V
    gemm_mma_kernel<<<dim3(EMB_ / 128, M_ / 128, 3), 256, GEMM_SMEM>>>(
        bq, bk, bv, nullptr, 0);

    // causal attention (mma.sync flash)
    attn_mma_kernel<<<dim3(S_ / 128, B_ * H_), 256, ATTN_SMEM>>>();

    // output projection (mma.sync)
    gemm_mma_kernel<<<dim3(EMB_ / 128, M_ / 128, 1), 256, GEMM_SMEM>>>(
        bo, nullptr, nullptr, out, 1);
}